// round 15
// baseline (speedup 1.0000x reference)
#include <cuda_runtime.h>
#include <cuda_bf16.h>
#include <math.h>
#include <stdint.h>

// Problem constants
#define E_  8
#define D_  1024
#define F_  4096
#define T_  8192
#define TK_ (T_ * 2)

// GEMM tiling: 128x128 block, 512 threads (16 warps, 4/SMSP), warp tile 32x32,
// KC=64 int8 chunk (64B rows, SW64 swizzle), 4-stage cp.async pipeline with
// pre-barrier issue.
#define BM 128
#define BN 128
#define KC 64
#define NTH 512
#define AH_OFF 0
#define AL_OFF 8192
#define BH_OFF 16384
#define BL_OFF 24576
#define STAGE_B 32768
#define NSTAGE 4
#define SMEM_DYN (NSTAGE * STAGE_B)   // 128 KB

#define INV127 0.007874015748031496f

// ---------------------------------------------------------------------------
// Device scratch (static: no allocations allowed)
// ---------------------------------------------------------------------------
__device__ int8_t g_xq_h[(size_t)T_ * D_];
__device__ int8_t g_xq_l[(size_t)T_ * D_];
__device__ int8_t g_wfq_h[(size_t)E_ * F_ * D_];
__device__ int8_t g_wfq_l[(size_t)E_ * F_ * D_];
__device__ int8_t g_wpq_h[(size_t)E_ * D_ * F_];
__device__ int8_t g_wpq_l[(size_t)E_ * D_ * F_];
__device__ int8_t g_hq_h[(size_t)TK_ * F_];
__device__ int8_t g_hq_l[(size_t)TK_ * F_];
__device__ float  g_h[(size_t)TK_ * F_];      // fp32 h before quantization
__device__ float  g_y[(size_t)TK_ * D_];      // per-slot proj output (no atomics)
__device__ float  g_sx[T_];
__device__ float  g_swf[E_ * F_];
__device__ float  g_swp[E_ * D_];
__device__ float  g_sh[TK_];
__device__ int    g_tok[E_ * T_];
__device__ float  g_wgt[E_ * T_];
__device__ int    g_se[TK_];                  // per token-slot: expert id
__device__ int    g_sp[TK_];                  // per token-slot: bucket position
__device__ int    g_cursor[E_];

// ---------------------------------------------------------------------------
// Helpers
// ---------------------------------------------------------------------------
static __device__ __forceinline__ uint32_t smem_u32(const void* p) {
    uint32_t a;
    asm("{ .reg .u64 t; cvta.to.shared.u64 t, %1; cvt.u32.u64 %0, t; }"
        : "=r"(a) : "l"(p));
    return a;
}

// 64B-row swizzle (validated R7/R8/R12/R14)
#define SW64(o) ((o) ^ (((o) >> 3) & 0x30))

#define CPA(dst, src) \
    asm volatile("cp.async.cg.shared.global [%0], [%1], 16;" \
                 :: "r"(dst), "l"(src) : "memory")
#define CPA_COMMIT() asm volatile("cp.async.commit_group;" ::: "memory")

#define LDSM4(r, addr) \
    asm volatile("ldmatrix.sync.aligned.m8n8.x4.shared.b16 {%0,%1,%2,%3}, [%4];" \
                 : "=r"((r)[0]), "=r"((r)[1]), "=r"((r)[2]), "=r"((r)[3]) \
                 : "r"(addr))

#define IMMA(cd, a, b0, b1) \
    asm volatile("mma.sync.aligned.m16n8k32.row.col.s32.s8.s8.s32 " \
                 "{%0,%1,%2,%3}, {%4,%5,%6,%7}, {%8,%9}, {%0,%1,%2,%3};" \
                 : "+r"((cd)[0]), "+r"((cd)[1]), "+r"((cd)[2]), "+r"((cd)[3]) \
                 : "r"((a)[0]), "r"((a)[1]), "r"((a)[2]), "r"((a)[3]), \
                   "r"(b0), "r"(b1))

static __device__ __forceinline__ float ngelu(float v) {
    float u = 0.7978845608028654f * (v + 0.044715f * v * v * v);
    return 0.5f * v * (1.0f + tanhf(u));
}

static __device__ __forceinline__ int expert_base(int e) {
    int b = 0;
#pragma unroll
    for (int j = 0; j < E_; j++) if (j < e) b += g_cursor[j];
    return b;
}

// Quantize one fp32 to (hi, lo) int8 given inv_s = 127/rowmax, s = rowmax/127
static __device__ __forceinline__ void q2(float v, float inv_s, float s,
                                          signed char& qh, signed char& ql) {
    int a = __float2int_rn(v * inv_s);
    float r = v - s * (float)a;
    int b = __float2int_rn(r * inv_s * 127.0f);
    qh = (signed char)a;
    ql = (signed char)b;
}

// One K=64 int8 chunk, register-lean term-by-term schedule (warp tile 32x32):
//   C0 += Ah*Bh;  C1 += Al*Bh;  (Bh regs overwritten with Bl)  C1 += Ah*Bl.
static __device__ __forceinline__ void mma_chunk_i8(
    uint32_t bufb, int warp_m, int warp_n,
    int rA, int bA, int rB, int bB, int (&c0)[2][4][4], int (&c1)[2][4][4]) {
#pragma unroll
    for (int ks = 0; ks < 2; ks++) {
        int kb = ks * 32;
        uint32_t Ah[2][4], Al[2][4], Bx[2][4];
#pragma unroll
        for (int f = 0; f < 2; f++) {
            uint32_t off = (uint32_t)((warp_m * 32 + f * 16 + rA) * 64 + kb + bA);
            LDSM4(Ah[f], bufb + AH_OFF + SW64(off));
        }
#pragma unroll
        for (int p = 0; p < 2; p++) {
            uint32_t off = (uint32_t)((warp_n * 32 + p * 16 + rB) * 64 + kb + bB);
            LDSM4(Bx[p], bufb + BH_OFF + SW64(off));
        }
#pragma unroll
        for (int f = 0; f < 2; f++)
#pragma unroll
            for (int nf = 0; nf < 4; nf++)
                IMMA(c0[f][nf], Ah[f], Bx[nf >> 1][(nf & 1) * 2], Bx[nf >> 1][(nf & 1) * 2 + 1]);
#pragma unroll
        for (int f = 0; f < 2; f++) {
            uint32_t off = (uint32_t)((warp_m * 32 + f * 16 + rA) * 64 + kb + bA);
            LDSM4(Al[f], bufb + AL_OFF + SW64(off));
        }
#pragma unroll
        for (int f = 0; f < 2; f++)
#pragma unroll
            for (int nf = 0; nf < 4; nf++)
                IMMA(c1[f][nf], Al[f], Bx[nf >> 1][(nf & 1) * 2], Bx[nf >> 1][(nf & 1) * 2 + 1]);
#pragma unroll
        for (int p = 0; p < 2; p++) {
            uint32_t off = (uint32_t)((warp_n * 32 + p * 16 + rB) * 64 + kb + bB);
            LDSM4(Bx[p], bufb + BL_OFF + SW64(off));
        }
#pragma unroll
        for (int f = 0; f < 2; f++)
#pragma unroll
            for (int nf = 0; nf < 4; nf++)
                IMMA(c1[f][nf], Ah[f], Bx[nf >> 1][(nf & 1) * 2], Bx[nf >> 1][(nf & 1) * 2 + 1]);
    }
}

// ---------------------------------------------------------------------------
// Kernel 0: reset cursors (out zeroing no longer needed: k_combine overwrites)
// ---------------------------------------------------------------------------
__global__ void k_reset() {
    if (threadIdx.x < E_) g_cursor[threadIdx.x] = 0;
}

// ---------------------------------------------------------------------------
// Kernel 1: gating (one warp per token); also records slot->(expert,pos)
// ---------------------------------------------------------------------------
__global__ void k_gate(const float* __restrict__ x, const float* __restrict__ gw) {
    int warp = threadIdx.x >> 5;
    int lane = threadIdx.x & 31;
    int t = blockIdx.x * 8 + warp;
    const float* xr = x + (size_t)t * D_;

    float xv[32];
#pragma unroll
    for (int i = 0; i < 32; i++) xv[i] = xr[i * 32 + lane];

    float logit[E_];
#pragma unroll
    for (int e = 0; e < E_; e++) {
        const float* wr = gw + e * D_;
        float acc = 0.f;
#pragma unroll
        for (int i = 0; i < 32; i++) acc = fmaf(xv[i], wr[i * 32 + lane], acc);
#pragma unroll
        for (int s = 16; s > 0; s >>= 1) acc += __shfl_xor_sync(0xffffffffu, acc, s);
        logit[e] = acc;
    }

    if (lane == 0) {
        int e0 = 0;
#pragma unroll
        for (int e = 1; e < E_; e++) if (logit[e] > logit[e0]) e0 = e;
        int e1 = (e0 == 0) ? 1 : 0;
#pragma unroll
        for (int e = 0; e < E_; e++) if (e != e0 && logit[e] > logit[e1]) e1 = e;

        float m  = logit[e0];
        float x0 = expf(logit[e0] - m);
        float x1 = expf(logit[e1] - m);
        float inv = 1.f / (x0 + x1);

        int p0 = atomicAdd(&g_cursor[e0], 1);
        g_tok[e0 * T_ + p0] = t;  g_wgt[e0 * T_ + p0] = x0 * inv;
        g_se[t * 2] = e0;  g_sp[t * 2] = p0;
        int p1 = atomicAdd(&g_cursor[e1], 1);
        g_tok[e1 * T_ + p1] = t;  g_wgt[e1 * T_ + p1] = x1 * inv;
        g_se[t * 2 + 1] = e1;  g_sp[t * 2 + 1] = p1;
    }
}

// ---------------------------------------------------------------------------
// Kernel 2: row-wise 2-level int8 quantization of x, wfc, wpj (256 threads)
// ---------------------------------------------------------------------------
#define QTH 256
__global__ void k_quantA(const float* __restrict__ x,
                         const float* __restrict__ wfc,
                         const float* __restrict__ wpj) {
    __shared__ float s_max[8];
    __shared__ float s_scale[2];
    int b = blockIdx.x, tid = threadIdx.x;

    const float* row; int8_t *qh, *ql; float* sc; int nvec;
    if (b < T_) {
        row = x + (size_t)b * D_;
        qh = g_xq_h + (size_t)b * D_;  ql = g_xq_l + (size_t)b * D_;
        sc = &g_sx[b]; nvec = 1;
    } else if (b < T_ + E_ * F_) {
        int r = b - T_;
        row = wfc + (size_t)r * D_;
        qh = g_wfq_h + (size_t)r * D_; ql = g_wfq_l + (size_t)r * D_;
        sc = &g_swf[r]; nvec = 1;
    } else {
        int r = b - T_ - E_ * F_;
        row = wpj + (size_t)r * F_;
        qh = g_wpq_h + (size_t)r * F_; ql = g_wpq_l + (size_t)r * F_;
        sc = &g_swp[r]; nvec = 4;
    }

    float4 v[4];
    float m = 0.f;
    for (int i = 0; i < nvec; i++) {
        v[i] = reinterpret_cast<const float4*>(row)[tid + i * QTH];
        m = fmaxf(m, fmaxf(fmaxf(fabsf(v[i].x), fabsf(v[i].y)),
                           fmaxf(fabsf(v[i].z), fabsf(v[i].w))));
    }
#pragma unroll
    for (int s = 16; s > 0; s >>= 1) m = fmaxf(m, __shfl_xor_sync(0xffffffffu, m, s));
    if ((tid & 31) == 0) s_max[tid >> 5] = m;
    __syncthreads();
    if (tid == 0) {
        float mm = s_max[0];
#pragma unroll
        for (int w = 1; w < 8; w++) mm = fmaxf(mm, s_max[w]);
        mm = fmaxf(mm, 1e-30f);
        s_scale[0] = mm / 127.0f;
        s_scale[1] = 127.0f / mm;
        *sc = mm / 127.0f;
    }
    __syncthreads();
    float s = s_scale[0], inv_s = s_scale[1];

    for (int i = 0; i < nvec; i++) {
        signed char h0, l0, h1, l1, h2, l2, h3, l3;
        q2(v[i].x, inv_s, s, h0, l0);
        q2(v[i].y, inv_s, s, h1, l1);
        q2(v[i].z, inv_s, s, h2, l2);
        q2(v[i].w, inv_s, s, h3, l3);
        reinterpret_cast<char4*>(qh)[tid + i * QTH] = make_char4(h0, h1, h2, h3);
        reinterpret_cast<char4*>(ql)[tid + i * QTH] = make_char4(l0, l1, l2, l3);
    }
}

// ---------------------------------------------------------------------------
// Kernel 4: row-wise quantization of h (bucket-ordered, rows of F)
// ---------------------------------------------------------------------------
__global__ void k_quantH() {
    __shared__ float s_max[8];
    __shared__ float s_scale[2];
    int b = blockIdx.x, tid = threadIdx.x;
    const float* row = g_h + (size_t)b * F_;
    int8_t* qh = g_hq_h + (size_t)b * F_;
    int8_t* ql = g_hq_l + (size_t)b * F_;

    float4 v[4];
    float m = 0.f;
#pragma unroll
    for (int i = 0; i < 4; i++) {
        v[i] = reinterpret_cast<const float4*>(row)[tid + i * QTH];
        m = fmaxf(m, fmaxf(fmaxf(fabsf(v[i].x), fabsf(v[i].y)),
                           fmaxf(fabsf(v[i].z), fabsf(v[i].w))));
    }
#pragma unroll
    for (int s = 16; s > 0; s >>= 1) m = fmaxf(m, __shfl_xor_sync(0xffffffffu, m, s));
    if ((tid & 31) == 0) s_max[tid >> 5] = m;
    __syncthreads();
    if (tid == 0) {
        float mm = s_max[0];
#pragma unroll
        for (int w = 1; w < 8; w++) mm = fmaxf(mm, s_max[w]);
        mm = fmaxf(mm, 1e-30f);
        s_scale[0] = mm / 127.0f;
        s_scale[1] = 127.0f / mm;
        g_sh[b] = mm / 127.0f;
    }
    __syncthreads();
    float s = s_scale[0], inv_s = s_scale[1];
#pragma unroll
    for (int i = 0; i < 4; i++) {
        signed char h0, l0, h1, l1, h2, l2, h3, l3;
        q2(v[i].x, inv_s, s, h0, l0);
        q2(v[i].y, inv_s, s, h1, l1);
        q2(v[i].z, inv_s, s, h2, l2);
        q2(v[i].w, inv_s, s, h3, l3);
        reinterpret_cast<char4*>(qh)[tid + i * QTH] = make_char4(h0, h1, h2, h3);
        reinterpret_cast<char4*>(ql)[tid + i * QTH] = make_char4(l0, l1, l2, l3);
    }
}

// ---------------------------------------------------------------------------
// Kernel 3: GEMM1  H = gelu(gather(Xq) @ Wfcq[e]^T + b) -> fp32 g_h
// grid (T/128, F/128, E), 512 threads, 4-stage pipeline, pre-barrier issue
// ---------------------------------------------------------------------------
__global__ void __launch_bounds__(NTH, 1)
k_fc_mma(const float* __restrict__ bfc) {
    int e = blockIdx.z;
    int cnt = g_cursor[e];
    int row0 = blockIdx.x * BM;
    if (row0 >= cnt) return;
    int n0 = blockIdx.y * BN;
    int hbase = expert_base(e);

    extern __shared__ __align__(1024) char smem[];
    __shared__ int s_toff[BM];
    int tid = threadIdx.x, wid = tid >> 5, lane = tid & 31;
    uint32_t sb = smem_u32(smem);

    if (tid < BM) s_toff[tid] = g_tok[e * T_ + min(row0 + tid, cnt - 1)] * D_;
    __syncthreads();

    int warp_m = wid >> 2, warp_n = wid & 3;   // 4 x 4 warps, tile 32x32
    int g = lane >> 3, l8 = lane & 7;
    int rA = (g & 1) * 8 + l8, bA = (g >> 1) * 16;
    int rB = (g >> 1) * 8 + l8, bB = (g & 1) * 16;

    int ur = tid >> 2, uc = tid & 3;

    const int8_t* wh = g_wfq_h + (size_t)e * F_ * D_;
    const int8_t* wl = g_wfq_l + (size_t)e * F_ * D_;

#define FC_ISSUE(ci)                                                            \
    {                                                                           \
        uint32_t bufb = sb + ((ci) & (NSTAGE - 1)) * STAGE_B;                   \
        int k0 = (ci) * KC;                                                     \
        uint32_t dst = SW64((uint32_t)(ur * 64 + uc * 16));                     \
        size_t ao = (size_t)s_toff[ur] + k0 + uc * 16;                          \
        size_t bo = (size_t)(n0 + ur) * D_ + k0 + uc * 16;                      \
        CPA(bufb + AH_OFF + dst, g_xq_h + ao);                                  \
        CPA(bufb + AL_OFF + dst, g_xq_l + ao);                                  \
        CPA(bufb + BH_OFF + dst, wh + bo);                                      \
        CPA(bufb + BL_OFF + dst, wl + bo);                                      \
        CPA_COMMIT();                                                           \
    }

    FC_ISSUE(0);
    FC_ISSUE(1);

    int c0[2][4][4], c1[2][4][4];
#pragma unroll
    for (int f = 0; f < 2; f++)
#pragma unroll
        for (int nf = 0; nf < 4; nf++)
#pragma unroll
            for (int q = 0; q < 4; q++) { c0[f][nf][q] = 0; c1[f][nf][q] = 0; }

    const int KCH = D_ / KC;   // 16
    for (int i = 0; i < KCH; i++) {
        // Pre-barrier issue: stage (i+2)%4 was last read at chunk i-2 (barriered)
        if (i + 2 < KCH) {
            FC_ISSUE(i + 2);
            asm volatile("cp.async.wait_group 2;" ::: "memory");
        } else if (i + 1 < KCH) {
            asm volatile("cp.async.wait_group 1;" ::: "memory");
        } else {
            asm volatile("cp.async.wait_group 0;" ::: "memory");
        }
        __syncthreads();
        mma_chunk_i8(sb + (i & (NSTAGE - 1)) * STAGE_B, warp_m, warp_n,
                     rA, bA, rB, bB, c0, c1);
        __syncthreads();
    }
#undef FC_ISSUE

    // Epilogue: scale-combine + bias + gelu -> fp32 g_h
    int qr = lane >> 2, qc = (lane & 3) * 2;
#pragma unroll
    for (int f = 0; f < 2; f++) {
#pragma unroll
        for (int pr = 0; pr < 2; pr++) {
            int rl = warp_m * 32 + f * 16 + qr + pr * 8;
            int r = row0 + rl;
            if (r >= cnt) continue;
            float sxv = g_sx[s_toff[rl] >> 10];   // token = offset / D_
            size_t hr = (size_t)(hbase + r);
#pragma unroll
            for (int nf = 0; nf < 4; nf++) {
                int n = n0 + warp_n * 32 + nf * 8 + qc;
                float sc0 = sxv * g_swf[e * F_ + n];
                float sc1 = sxv * g_swf[e * F_ + n + 1];
                float a0 = (float)c0[f][nf][pr * 2 + 0] + (float)c1[f][nf][pr * 2 + 0] * INV127;
                float a1 = (float)c0[f][nf][pr * 2 + 1] + (float)c1[f][nf][pr * 2 + 1] * INV127;
                float v0 = ngelu(a0 * sc0 + bfc[e * F_ + n]);
                float v1 = ngelu(a1 * sc1 + bfc[e * F_ + n + 1]);
                *reinterpret_cast<float2*>(g_h + hr * F_ + n) = make_float2(v0, v1);
            }
        }
    }
}

// ---------------------------------------------------------------------------
// Kernel 5: GEMM2  y[slot] = Hq @ Wprojq[e]^T  (no bias/weight; plain stores)
// grid (T/128, D/128, E), 512 threads
// ---------------------------------------------------------------------------
__global__ void __launch_bounds__(NTH, 1)
k_proj_mma() {
    int e = blockIdx.z;
    int cnt = g_cursor[e];
    int row0 = blockIdx.x * BM;
    if (row0 >= cnt) return;
    int n0 = blockIdx.y * BN;
    int hbase = expert_base(e);

    extern __shared__ __align__(1024) char smem[];
    __shared__ int s_hrow[BM];
    int tid = threadIdx.x, wid = tid >> 5, lane = tid & 31;
    uint32_t sb = smem_u32(smem);

    if (tid < BM) s_hrow[tid] = hbase + min(row0 + tid, cnt - 1);
    __syncthreads();

    int warp_m = wid >> 2, warp_n = wid & 3;
    int g = lane >> 3, l8 = lane & 7;
    int rA = (g & 1) * 8 + l8, bA = (g >> 1) * 16;
    int rB = (g >> 1) * 8 + l8, bB = (g & 1) * 16;

    int ur = tid >> 2, uc = tid & 3;

    const int8_t* wh = g_wpq_h + (size_t)e * D_ * F_;
    const int8_t* wl = g_wpq_l + (size_t)e * D_ * F_;

#define PJ_ISSUE(ci)                                                            \
    {                                                                           \
        uint32_t bufb = sb + ((ci) & (NSTAGE - 1)) * STAGE_B;                   \
        int k0 = (ci) * KC;                                                     \
        uint32_t dst = SW64((uint32_t)(ur * 64 + uc * 16));                     \
        size_t ao = (size_t)s_hrow[ur] * F_ + k0 + uc * 16;                     \
        size_t bo = (size_t)(n0 + ur) * F_ + k0 + uc * 16;                      \
        CPA(bufb + AH_OFF + dst, g_hq_h + ao);                                  \
        CPA(bufb + AL_OFF + dst, g_hq_l + ao);                                  \
        CPA(bufb + BH_OFF + dst, wh + bo);                                      \
        CPA(bufb + BL_OFF + dst, wl + bo);                                      \
        CPA_COMMIT();                                                           \
    }

    PJ_ISSUE(0);
    PJ_ISSUE(1);

    int c0[2][4][4], c1[2][4][4];
#pragma unroll
    for (int f = 0; f < 2; f++)
#pragma unroll
        for (int nf = 0; nf < 4; nf++)
#pragma unroll
            for (int q = 0; q < 4; q++) { c0[f][nf][q] = 0; c1[f][nf][q] = 0; }

    const int KCH = F_ / KC;   // 64
    for (int i = 0; i < KCH; i++) {
        if (i + 2 < KCH) {
            PJ_ISSUE(i + 2);
            asm volatile("cp.async.wait_group 2;" ::: "memory");
        } else if (i + 1 < KCH) {
            asm volatile("cp.async.wait_group 1;" ::: "memory");
        } else {
            asm volatile("cp.async.wait_group 0;" ::: "memory");
        }
        __syncthreads();
        mma_chunk_i8(sb + (i & (NSTAGE - 1)) * STAGE_B, warp_m, warp_n,
                     rA, bA, rB, bB, c0, c1);
        __syncthreads();
    }
#undef PJ_ISSUE

    // Epilogue: y = acc * scale, plain store to per-slot buffer
    int qr = lane >> 2, qc = (lane & 3) * 2;
#pragma unroll
    for (int f = 0; f < 2; f++) {
#pragma unroll
        for (int pr = 0; pr < 2; pr++) {
            int rl = warp_m * 32 + f * 16 + qr + pr * 8;
            int r = row0 + rl;
            if (r >= cnt) continue;
            float shv = g_sh[s_hrow[rl]];
            float* yrow = g_y + (size_t)s_hrow[rl] * D_;
#pragma unroll
            for (int nf = 0; nf < 4; nf++) {
                int n = n0 + warp_n * 32 + nf * 8 + qc;
                float sc0 = shv * g_swp[e * D_ + n];
                float sc1 = shv * g_swp[e * D_ + n + 1];
                float a0 = (float)c0[f][nf][pr * 2 + 0] + (float)c1[f][nf][pr * 2 + 0] * INV127;
                float a1 = (float)c0[f][nf][pr * 2 + 1] + (float)c1[f][nf][pr * 2 + 1] * INV127;
                *reinterpret_cast<float2*>(yrow + n) = make_float2(a0 * sc0, a1 * sc1);
            }
        }
    }
}

// ---------------------------------------------------------------------------
// Kernel 6: combine  out[t] = w0*(y0 + b[e0]) + w1*(y1 + b[e1])
// grid T_ blocks x 256 threads (1 float4 per thread)
// ---------------------------------------------------------------------------
__global__ void k_combine(const float* __restrict__ bpj, float* __restrict__ out) {
    int t = blockIdx.x, tid = threadIdx.x;
    int e0 = g_se[t * 2],     p0 = g_sp[t * 2];
    int e1 = g_se[t * 2 + 1], p1 = g_sp[t * 2 + 1];
    int r0 = expert_base(e0) + p0;
    int r1 = expert_base(e1) + p1;
    float w0 = g_wgt[e0 * T_ + p0];
    float w1 = g_wgt[e1 * T_ + p1];

    const float4* y0 = reinterpret_cast<const float4*>(g_y + (size_t)r0 * D_);
    const float4* y1 = reinterpret_cast<const float4*>(g_y + (size_t)r1 * D_);
    const float4* b0 = reinterpret_cast<const float4*>(bpj + e0 * D_);
    const float4* b1 = reinterpret_cast<const float4*>(bpj + e1 * D_);
    float4* o = reinterpret_cast<float4*>(out + (size_t)t * D_);

    float4 a = y0[tid], b = y1[tid], c = b0[tid], d = b1[tid];
    float4 r;
    r.x = (a.x + c.x) * w0 + (b.x + d.x) * w1;
    r.y = (a.y + c.y) * w0 + (b.y + d.y) * w1;
    r.z = (a.z + c.z) * w0 + (b.z + d.z) * w1;
    r.w = (a.w + c.w) * w0 + (b.w + d.w) * w1;
    o[tid] = r;
}

// ---------------------------------------------------------------------------
// Launch: reset, gate, quantA, fc (ncu slot 3), quantH, proj, combine
// ---------------------------------------------------------------------------
extern "C" void kernel_launch(void* const* d_in, const int* in_sizes, int n_in,
                              void* d_out, int out_size) {
    const float* x   = (const float*)d_in[0];
    const float* gw  = (const float*)d_in[1];
    const float* wfc = (const float*)d_in[2];
    const float* bfc = (const float*)d_in[3];
    const float* wpj = (const float*)d_in[4];
    const float* bpj = (const float*)d_in[5];
    float* out = (float*)d_out;

    cudaFuncSetAttribute(k_fc_mma,   cudaFuncAttributeMaxDynamicSharedMemorySize, SMEM_DYN);
    cudaFuncSetAttribute(k_proj_mma, cudaFuncAttributeMaxDynamicSharedMemorySize, SMEM_DYN);

    k_reset <<<1, 32>>>();                                                     // 0
    k_gate  <<<T_ / 8, 256>>>(x, gw);                                          // 1
    k_quantA<<<T_ + E_ * F_ + E_ * D_, QTH>>>(x, wfc, wpj);                    // 2
    k_fc_mma  <<<dim3(T_ / BM, F_ / BN, E_), NTH, SMEM_DYN>>>(bfc);            // 3 <- ncu
    k_quantH<<<TK_, QTH>>>();                                                  // 4
    k_proj_mma<<<dim3(T_ / BM, D_ / BN, E_), NTH, SMEM_DYN>>>();               // 5
    k_combine<<<T_, 256>>>(bpj, out);                                          // 6
}

// round 16
// speedup vs baseline: 1.0569x; 1.0569x over previous
#include <cuda_runtime.h>
#include <cuda_bf16.h>
#include <math.h>
#include <stdint.h>

// Problem constants
#define E_  8
#define D_  1024
#define F_  4096
#define T_  8192
#define TK_ (T_ * 2)

// GEMM tiling: 128x128 block, 512 threads (16 warps, 4/SMSP), warp tile 32x32,
// KC=64 int8 chunk (64B rows, SW64 swizzle), 3-stage cp.async pipeline.
#define BM 128
#define BN 128
#define KC 64
#define NTH 512
#define AH_OFF 0
#define AL_OFF 8192
#define BH_OFF 16384
#define BL_OFF 24576
#define STAGE_B 32768
#define NSTAGE 3
#define SMEM_DYN (NSTAGE * STAGE_B)   // 96 KB

#define INV127 0.007874015748031496f

// ---------------------------------------------------------------------------
// Device scratch (static: no allocations allowed)
// ---------------------------------------------------------------------------
__device__ int8_t g_xq_h[(size_t)T_ * D_];
__device__ int8_t g_xq_l[(size_t)T_ * D_];
__device__ int8_t g_wfq_h[(size_t)E_ * F_ * D_];
__device__ int8_t g_wfq_l[(size_t)E_ * F_ * D_];
__device__ int8_t g_wpq_h[(size_t)E_ * D_ * F_];
__device__ int8_t g_wpq_l[(size_t)E_ * D_ * F_];
__device__ int8_t g_hq_h[(size_t)TK_ * F_];
__device__ int8_t g_hq_l[(size_t)TK_ * F_];
__device__ float  g_h[(size_t)TK_ * F_];      // fp32 h before quantization
__device__ float  g_sx[T_];
__device__ float  g_swf[E_ * F_];
__device__ float  g_swp[E_ * D_];
__device__ float  g_sh[TK_];
__device__ int    g_tok[E_ * T_];
__device__ float  g_wgt[E_ * T_];
__device__ int    g_cursor[E_];

// ---------------------------------------------------------------------------
// Helpers
// ---------------------------------------------------------------------------
static __device__ __forceinline__ uint32_t smem_u32(const void* p) {
    uint32_t a;
    asm("{ .reg .u64 t; cvta.to.shared.u64 t, %1; cvt.u32.u64 %0, t; }"
        : "=r"(a) : "l"(p));
    return a;
}

// 64B-row swizzle (validated R7/R8/R12/R14)
#define SW64(o) ((o) ^ (((o) >> 3) & 0x30))

#define CPA(dst, src) \
    asm volatile("cp.async.cg.shared.global [%0], [%1], 16;" \
                 :: "r"(dst), "l"(src) : "memory")
#define CPA_COMMIT() asm volatile("cp.async.commit_group;" ::: "memory")

#define LDSM4(r, addr) \
    asm volatile("ldmatrix.sync.aligned.m8n8.x4.shared.b16 {%0,%1,%2,%3}, [%4];" \
                 : "=r"((r)[0]), "=r"((r)[1]), "=r"((r)[2]), "=r"((r)[3]) \
                 : "r"(addr))

#define IMMA(cd, a, b0, b1) \
    asm volatile("mma.sync.aligned.m16n8k32.row.col.s32.s8.s8.s32 " \
                 "{%0,%1,%2,%3}, {%4,%5,%6,%7}, {%8,%9}, {%0,%1,%2,%3};" \
                 : "+r"((cd)[0]), "+r"((cd)[1]), "+r"((cd)[2]), "+r"((cd)[3]) \
                 : "r"((a)[0]), "r"((a)[1]), "r"((a)[2]), "r"((a)[3]), \
                   "r"(b0), "r"(b1))

static __device__ __forceinline__ float ngelu(float v) {
    float u = 0.7978845608028654f * (v + 0.044715f * v * v * v);
    return 0.5f * v * (1.0f + tanhf(u));
}

static __device__ __forceinline__ int expert_base(int e) {
    int b = 0;
#pragma unroll
    for (int j = 0; j < E_; j++) if (j < e) b += g_cursor[j];
    return b;
}

// Quantize one fp32 to (hi, lo) int8 given inv_s = 127/rowmax, s = rowmax/127
static __device__ __forceinline__ void q2(float v, float inv_s, float s,
                                          signed char& qh, signed char& ql) {
    int a = __float2int_rn(v * inv_s);
    float r = v - s * (float)a;
    int b = __float2int_rn(r * inv_s * 127.0f);
    qh = (signed char)a;
    ql = (signed char)b;
}

// One K=64 int8 chunk, register-lean term-by-term schedule (warp tile 32x32):
//   C0 += Ah*Bh;  C1 += Al*Bh;  (Bh regs overwritten with Bl)  C1 += Ah*Bl.
static __device__ __forceinline__ void mma_chunk_i8(
    uint32_t bufb, int warp_m, int warp_n,
    int rA, int bA, int rB, int bB, int (&c0)[2][4][4], int (&c1)[2][4][4]) {
#pragma unroll
    for (int ks = 0; ks < 2; ks++) {
        int kb = ks * 32;
        uint32_t Ah[2][4], Al[2][4], Bx[2][4];
#pragma unroll
        for (int f = 0; f < 2; f++) {
            uint32_t off = (uint32_t)((warp_m * 32 + f * 16 + rA) * 64 + kb + bA);
            LDSM4(Ah[f], bufb + AH_OFF + SW64(off));
        }
#pragma unroll
        for (int p = 0; p < 2; p++) {
            uint32_t off = (uint32_t)((warp_n * 32 + p * 16 + rB) * 64 + kb + bB);
            LDSM4(Bx[p], bufb + BH_OFF + SW64(off));
        }
#pragma unroll
        for (int f = 0; f < 2; f++)
#pragma unroll
            for (int nf = 0; nf < 4; nf++)
                IMMA(c0[f][nf], Ah[f], Bx[nf >> 1][(nf & 1) * 2], Bx[nf >> 1][(nf & 1) * 2 + 1]);
#pragma unroll
        for (int f = 0; f < 2; f++) {
            uint32_t off = (uint32_t)((warp_m * 32 + f * 16 + rA) * 64 + kb + bA);
            LDSM4(Al[f], bufb + AL_OFF + SW64(off));
        }
#pragma unroll
        for (int f = 0; f < 2; f++)
#pragma unroll
            for (int nf = 0; nf < 4; nf++)
                IMMA(c1[f][nf], Al[f], Bx[nf >> 1][(nf & 1) * 2], Bx[nf >> 1][(nf & 1) * 2 + 1]);
#pragma unroll
        for (int p = 0; p < 2; p++) {
            uint32_t off = (uint32_t)((warp_n * 32 + p * 16 + rB) * 64 + kb + bB);
            LDSM4(Bx[p], bufb + BL_OFF + SW64(off));
        }
#pragma unroll
        for (int f = 0; f < 2; f++)
#pragma unroll
            for (int nf = 0; nf < 4; nf++)
                IMMA(c1[f][nf], Ah[f], Bx[nf >> 1][(nf & 1) * 2], Bx[nf >> 1][(nf & 1) * 2 + 1]);
    }
}

// ---------------------------------------------------------------------------
// Kernel 0: reset cursors + zero output
// ---------------------------------------------------------------------------
__global__ void k_zero(float* __restrict__ out, int n_elems) {
    if (blockIdx.x == 0 && threadIdx.x < E_) g_cursor[threadIdx.x] = 0;
    int i = blockIdx.x * blockDim.x + threadIdx.x;
    int stride = gridDim.x * blockDim.x;
    float4 z = make_float4(0.f, 0.f, 0.f, 0.f);
    for (int idx = i; idx * 4 < n_elems; idx += stride)
        reinterpret_cast<float4*>(out)[idx] = z;
}

// ---------------------------------------------------------------------------
// Kernel 1: gating (one warp per token)
// ---------------------------------------------------------------------------
__global__ void k_gate(const float* __restrict__ x, const float* __restrict__ gw) {
    int warp = threadIdx.x >> 5;
    int lane = threadIdx.x & 31;
    int t = blockIdx.x * 8 + warp;
    const float* xr = x + (size_t)t * D_;

    float xv[32];
#pragma unroll
    for (int i = 0; i < 32; i++) xv[i] = xr[i * 32 + lane];

    float logit[E_];
#pragma unroll
    for (int e = 0; e < E_; e++) {
        const float* wr = gw + e * D_;
        float acc = 0.f;
#pragma unroll
        for (int i = 0; i < 32; i++) acc = fmaf(xv[i], wr[i * 32 + lane], acc);
#pragma unroll
        for (int s = 16; s > 0; s >>= 1) acc += __shfl_xor_sync(0xffffffffu, acc, s);
        logit[e] = acc;
    }

    if (lane == 0) {
        int e0 = 0;
#pragma unroll
        for (int e = 1; e < E_; e++) if (logit[e] > logit[e0]) e0 = e;
        int e1 = (e0 == 0) ? 1 : 0;
#pragma unroll
        for (int e = 0; e < E_; e++) if (e != e0 && logit[e] > logit[e1]) e1 = e;

        float m  = logit[e0];
        float x0 = expf(logit[e0] - m);
        float x1 = expf(logit[e1] - m);
        float inv = 1.f / (x0 + x1);

        int p0 = atomicAdd(&g_cursor[e0], 1);
        g_tok[e0 * T_ + p0] = t;  g_wgt[e0 * T_ + p0] = x0 * inv;
        int p1 = atomicAdd(&g_cursor[e1], 1);
        g_tok[e1 * T_ + p1] = t;  g_wgt[e1 * T_ + p1] = x1 * inv;
    }
}

// ---------------------------------------------------------------------------
// Kernel 2a: warp-per-row quantization for D=1024 rows (x and wfc).
// 8 warps/block = 8 rows/block; shuffle-only reduction, no __syncthreads.
// Row r: r < T_ -> x row; else wfc row (r - T_).
// ---------------------------------------------------------------------------
#define QTH 256
#define NROWS_D (T_ + E_ * F_)      // 8192 + 32768 = 40960 rows

__global__ void k_quantD(const float* __restrict__ x,
                         const float* __restrict__ wfc) {
    int warp = threadIdx.x >> 5;
    int lane = threadIdx.x & 31;
    int r = blockIdx.x * 8 + warp;
    if (r >= NROWS_D) return;

    const float* row; int8_t *qh, *ql; float* sc;
    if (r < T_) {
        row = x + (size_t)r * D_;
        qh = g_xq_h + (size_t)r * D_;  ql = g_xq_l + (size_t)r * D_;
        sc = &g_sx[r];
    } else {
        int w = r - T_;
        row = wfc + (size_t)w * D_;
        qh = g_wfq_h + (size_t)w * D_; ql = g_wfq_l + (size_t)w * D_;
        sc = &g_swf[w];
    }

    // 1024 floats / 32 lanes = 8 float4 per lane
    float4 v[8];
    float m = 0.f;
#pragma unroll
    for (int i = 0; i < 8; i++) {
        v[i] = reinterpret_cast<const float4*>(row)[lane + i * 32];
        m = fmaxf(m, fmaxf(fmaxf(fabsf(v[i].x), fabsf(v[i].y)),
                           fmaxf(fabsf(v[i].z), fabsf(v[i].w))));
    }
#pragma unroll
    for (int s = 16; s > 0; s >>= 1) m = fmaxf(m, __shfl_xor_sync(0xffffffffu, m, s));
    m = fmaxf(m, 1e-30f);
    float s = m / 127.0f, inv_s = 127.0f / m;
    if (lane == 0) *sc = s;

#pragma unroll
    for (int i = 0; i < 8; i++) {
        signed char h0, l0, h1, l1, h2, l2, h3, l3;
        q2(v[i].x, inv_s, s, h0, l0);
        q2(v[i].y, inv_s, s, h1, l1);
        q2(v[i].z, inv_s, s, h2, l2);
        q2(v[i].w, inv_s, s, h3, l3);
        reinterpret_cast<char4*>(qh)[lane + i * 32] = make_char4(h0, h1, h2, h3);
        reinterpret_cast<char4*>(ql)[lane + i * 32] = make_char4(l0, l1, l2, l3);
    }
}

// ---------------------------------------------------------------------------
// Kernel 2b: block-per-row quantization for F=4096 rows (wpj).
// ---------------------------------------------------------------------------
__global__ void k_quantF(const float* __restrict__ wpj) {
    __shared__ float s_max[8];
    __shared__ float s_scale[2];
    int r = blockIdx.x, tid = threadIdx.x;
    const float* row = wpj + (size_t)r * F_;
    int8_t* qh = g_wpq_h + (size_t)r * F_;
    int8_t* ql = g_wpq_l + (size_t)r * F_;

    float4 v[4];
    float m = 0.f;
#pragma unroll
    for (int i = 0; i < 4; i++) {
        v[i] = reinterpret_cast<const float4*>(row)[tid + i * QTH];
        m = fmaxf(m, fmaxf(fmaxf(fabsf(v[i].x), fabsf(v[i].y)),
                           fmaxf(fabsf(v[i].z), fabsf(v[i].w))));
    }
#pragma unroll
    for (int s = 16; s > 0; s >>= 1) m = fmaxf(m, __shfl_xor_sync(0xffffffffu, m, s));
    if ((tid & 31) == 0) s_max[tid >> 5] = m;
    __syncthreads();
    if (tid == 0) {
        float mm = s_max[0];
#pragma unroll
        for (int w = 1; w < 8; w++) mm = fmaxf(mm, s_max[w]);
        mm = fmaxf(mm, 1e-30f);
        s_scale[0] = mm / 127.0f;
        s_scale[1] = 127.0f / mm;
        g_swp[r] = mm / 127.0f;
    }
    __syncthreads();
    float s = s_scale[0], inv_s = s_scale[1];
#pragma unroll
    for (int i = 0; i < 4; i++) {
        signed char h0, l0, h1, l1, h2, l2, h3, l3;
        q2(v[i].x, inv_s, s, h0, l0);
        q2(v[i].y, inv_s, s, h1, l1);
        q2(v[i].z, inv_s, s, h2, l2);
        q2(v[i].w, inv_s, s, h3, l3);
        reinterpret_cast<char4*>(qh)[tid + i * QTH] = make_char4(h0, h1, h2, h3);
        reinterpret_cast<char4*>(ql)[tid + i * QTH] = make_char4(l0, l1, l2, l3);
    }
}

// ---------------------------------------------------------------------------
// Kernel 4: row-wise quantization of h (bucket-ordered, rows of F)
// ---------------------------------------------------------------------------
__global__ void k_quantH() {
    __shared__ float s_max[8];
    __shared__ float s_scale[2];
    int b = blockIdx.x, tid = threadIdx.x;
    const float* row = g_h + (size_t)b * F_;
    int8_t* qh = g_hq_h + (size_t)b * F_;
    int8_t* ql = g_hq_l + (size_t)b * F_;

    float4 v[4];
    float m = 0.f;
#pragma unroll
    for (int i = 0; i < 4; i++) {
        v[i] = reinterpret_cast<const float4*>(row)[tid + i * QTH];
        m = fmaxf(m, fmaxf(fmaxf(fabsf(v[i].x), fabsf(v[i].y)),
                           fmaxf(fabsf(v[i].z), fabsf(v[i].w))));
    }
#pragma unroll
    for (int s = 16; s > 0; s >>= 1) m = fmaxf(m, __shfl_xor_sync(0xffffffffu, m, s));
    if ((tid & 31) == 0) s_max[tid >> 5] = m;
    __syncthreads();
    if (tid == 0) {
        float mm = s_max[0];
#pragma unroll
        for (int w = 1; w < 8; w++) mm = fmaxf(mm, s_max[w]);
        mm = fmaxf(mm, 1e-30f);
        s_scale[0] = mm / 127.0f;
        s_scale[1] = 127.0f / mm;
        g_sh[b] = mm / 127.0f;
    }
    __syncthreads();
    float s = s_scale[0], inv_s = s_scale[1];
#pragma unroll
    for (int i = 0; i < 4; i++) {
        signed char h0, l0, h1, l1, h2, l2, h3, l3;
        q2(v[i].x, inv_s, s, h0, l0);
        q2(v[i].y, inv_s, s, h1, l1);
        q2(v[i].z, inv_s, s, h2, l2);
        q2(v[i].w, inv_s, s, h3, l3);
        reinterpret_cast<char4*>(qh)[tid + i * QTH] = make_char4(h0, h1, h2, h3);
        reinterpret_cast<char4*>(ql)[tid + i * QTH] = make_char4(l0, l1, l2, l3);
    }
}

// ---------------------------------------------------------------------------
// Kernel 3: GEMM1  H = gelu(gather(Xq) @ Wfcq[e]^T + b) -> fp32 g_h
// grid (T/128, F/128, E), 512 threads, warp tile 32x32, int8 IMMA (R14-proven)
// ---------------------------------------------------------------------------
__global__ void __launch_bounds__(NTH, 1)
k_fc_mma(const float* __restrict__ bfc) {
    int e = blockIdx.z;
    int cnt = g_cursor[e];
    int row0 = blockIdx.x * BM;
    if (row0 >= cnt) return;
    int n0 = blockIdx.y * BN;
    int hbase = expert_base(e);

    extern __shared__ __align__(1024) char smem[];
    __shared__ int s_toff[BM];
    int tid = threadIdx.x, wid = tid >> 5, lane = tid & 31;
    uint32_t sb = smem_u32(smem);

    if (tid < BM) s_toff[tid] = g_tok[e * T_ + min(row0 + tid, cnt - 1)] * D_;
    __syncthreads();

    int warp_m = wid >> 2, warp_n = wid & 3;   // 4 x 4 warps, tile 32x32
    int g = lane >> 3, l8 = lane & 7;
    int rA = (g & 1) * 8 + l8, bA = (g >> 1) * 16;
    int rB = (g >> 1) * 8 + l8, bB = (g & 1) * 16;

    int ur = tid >> 2, uc = tid & 3;

    const int8_t* wh = g_wfq_h + (size_t)e * F_ * D_;
    const int8_t* wl = g_wfq_l + (size_t)e * F_ * D_;

#define FC_ISSUE(ci, sg)                                                        \
    {                                                                           \
        uint32_t bufb = sb + (sg) * STAGE_B;                                    \
        int k0 = (ci) * KC;                                                     \
        uint32_t dst = SW64((uint32_t)(ur * 64 + uc * 16));                     \
        size_t ao = (size_t)s_toff[ur] + k0 + uc * 16;                          \
        size_t bo = (size_t)(n0 + ur) * D_ + k0 + uc * 16;                      \
        CPA(bufb + AH_OFF + dst, g_xq_h + ao);                                  \
        CPA(bufb + AL_OFF + dst, g_xq_l + ao);                                  \
        CPA(bufb + BH_OFF + dst, wh + bo);                                      \
        CPA(bufb + BL_OFF + dst, wl + bo);                                      \
        CPA_COMMIT();                                                           \
    }

    FC_ISSUE(0, 0);
    FC_ISSUE(1, 1);

    int c0[2][4][4], c1[2][4][4];
#pragma unroll
    for (int f = 0; f < 2; f++)
#pragma unroll
        for (int nf = 0; nf < 4; nf++)
#pragma unroll
            for (int q = 0; q < 4; q++) { c0[f][nf][q] = 0; c1[f][nf][q] = 0; }

    const int KCH = D_ / KC;   // 16
    int stage = 0;
    for (int i = 0; i < KCH; i++) {
        if (i < KCH - 1) asm volatile("cp.async.wait_group 1;" ::: "memory");
        else             asm volatile("cp.async.wait_group 0;" ::: "memory");
        __syncthreads();
        if (i + 2 < KCH) {
            int sg = stage + 2; if (sg >= NSTAGE) sg -= NSTAGE;
            FC_ISSUE(i + 2, sg);
        }
        mma_chunk_i8(sb + stage * STAGE_B, warp_m, warp_n, rA, bA, rB, bB, c0, c1);
        if (++stage == NSTAGE) stage = 0;
    }
#undef FC_ISSUE

    // Epilogue: scale-combine + bias + gelu -> fp32 g_h
    int qr = lane >> 2, qc = (lane & 3) * 2;
#pragma unroll
    for (int f = 0; f < 2; f++) {
#pragma unroll
        for (int pr = 0; pr < 2; pr++) {
            int rl = warp_m * 32 + f * 16 + qr + pr * 8;
            int r = row0 + rl;
            if (r >= cnt) continue;
            float sxv = g_sx[s_toff[rl] >> 10];   // token = offset / D_
            size_t hr = (size_t)(hbase + r);
#pragma unroll
            for (int nf = 0; nf < 4; nf++) {
                int n = n0 + warp_n * 32 + nf * 8 + qc;
                float sc0 = sxv * g_swf[e * F_ + n];
                float sc1 = sxv * g_swf[e * F_ + n + 1];
                float a0 = (float)c0[f][nf][pr * 2 + 0] + (float)c1[f][nf][pr * 2 + 0] * INV127;
                float a1 = (float)c0[f][nf][pr * 2 + 1] + (float)c1[f][nf][pr * 2 + 1] * INV127;
                float v0 = ngelu(a0 * sc0 + bfc[e * F_ + n]);
                float v1 = ngelu(a1 * sc1 + bfc[e * F_ + n + 1]);
                *reinterpret_cast<float2*>(g_h + hr * F_ + n) = make_float2(v0, v1);
            }
        }
    }
}

// ---------------------------------------------------------------------------
// Kernel 5: GEMM2  out[token] += w * (Hq @ Wprojq[e]^T + b)
// grid (T/128, D/128, E), 512 threads (R14-proven, atomic scatter)
// ---------------------------------------------------------------------------
__global__ void __launch_bounds__(NTH, 1)
k_proj_mma(const float* __restrict__ bpj, float* __restrict__ out) {
    int e = blockIdx.z;
    int cnt = g_cursor[e];
    int row0 = blockIdx.x * BM;
    if (row0 >= cnt) return;
    int n0 = blockIdx.y * BN;
    int hbase = expert_base(e);

    extern __shared__ __align__(1024) char smem[];
    __shared__ int   s_hrow[BM];
    __shared__ int   s_tok[BM];
    __shared__ float s_wgt[BM];
    int tid = threadIdx.x, wid = tid >> 5, lane = tid & 31;
    uint32_t sb = smem_u32(smem);

    if (tid < BM) {
        int r = min(row0 + tid, cnt - 1);
        s_hrow[tid] = hbase + r;
        s_tok[tid]  = g_tok[e * T_ + r];
        s_wgt[tid]  = g_wgt[e * T_ + r];
    }
    __syncthreads();

    int warp_m = wid >> 2, warp_n = wid & 3;
    int g = lane >> 3, l8 = lane & 7;
    int rA = (g & 1) * 8 + l8, bA = (g >> 1) * 16;
    int rB = (g >> 1) * 8 + l8, bB = (g & 1) * 16;

    int ur = tid >> 2, uc = tid & 3;

    const int8_t* wh = g_wpq_h + (size_t)e * D_ * F_;
    const int8_t* wl = g_wpq_l + (size_t)e * D_ * F_;

#define PJ_ISSUE(ci, sg)                                                        \
    {                                                                           \
        uint32_t bufb = sb + (sg) * STAGE_B;                                    \
        int k0 = (ci) * KC;                                                     \
        uint32_t dst = SW64((uint32_t)(ur * 64 + uc * 16));                     \
        size_t ao = (size_t)s_hrow[ur] * F_ + k0 + uc * 16;                     \
        size_t bo = (size_t)(n0 + ur) * F_ + k0 + uc * 16;                      \
        CPA(bufb + AH_OFF + dst, g_hq_h + ao);                                  \
        CPA(bufb + AL_OFF + dst, g_hq_l + ao);                                  \
        CPA(bufb + BH_OFF + dst, wh + bo);                                      \
        CPA(bufb + BL_OFF + dst, wl + bo);                                      \
        CPA_COMMIT();                                                           \
    }

    PJ_ISSUE(0, 0);
    PJ_ISSUE(1, 1);

    int c0[2][4][4], c1[2][4][4];
#pragma unroll
    for (int f = 0; f < 2; f++)
#pragma unroll
        for (int nf = 0; nf < 4; nf++)
#pragma unroll
            for (int q = 0; q < 4; q++) { c0[f][nf][q] = 0; c1[f][nf][q] = 0; }

    const int KCH = F_ / KC;   // 64
    int stage = 0;
    for (int i = 0; i < KCH; i++) {
        if (i < KCH - 1) asm volatile("cp.async.wait_group 1;" ::: "memory");
        else             asm volatile("cp.async.wait_group 0;" ::: "memory");
        __syncthreads();
        if (i + 2 < KCH) {
            int sg = stage + 2; if (sg >= NSTAGE) sg -= NSTAGE;
            PJ_ISSUE(i + 2, sg);
        }
        mma_chunk_i8(sb + stage * STAGE_B, warp_m, warp_n, rA, bA, rB, bB, c0, c1);
        if (++stage == NSTAGE) stage = 0;
    }
#undef PJ_ISSUE

    // Epilogue: scale-combine + bias, * routing weight, atomic scatter
    int qr = lane >> 2, qc = (lane & 3) * 2;
#pragma unroll
    for (int f = 0; f < 2; f++) {
#pragma unroll
        for (int pr = 0; pr < 2; pr++) {
            int rl = warp_m * 32 + f * 16 + qr + pr * 8;
            int r = row0 + rl;
            if (r >= cnt) continue;
            int   token = s_tok[rl];
            float w     = s_wgt[rl];
            float shv   = g_sh[s_hrow[rl]];
            float* orow = out + (size_t)token * D_;
#pragma unroll
            for (int nf = 0; nf < 4; nf++) {
                int n = n0 + warp_n * 32 + nf * 8 + qc;
                float sc0 = shv * g_swp[e * D_ + n];
                float sc1 = shv * g_swp[e * D_ + n + 1];
                float a0 = (float)c0[f][nf][pr * 2 + 0] + (float)c1[f][nf][pr * 2 + 0] * INV127;
                float a1 = (float)c0[f][nf][pr * 2 + 1] + (float)c1[f][nf][pr * 2 + 1] * INV127;
                atomicAdd(orow + n,     (a0 * sc0 + bpj[e * D_ + n])     * w);
                atomicAdd(orow + n + 1, (a1 * sc1 + bpj[e * D_ + n + 1]) * w);
            }
        }
    }
}

// ---------------------------------------------------------------------------
// Launch: zero, gate, quantD, fc (ncu slot 3), quantF, quantH, proj
// ---------------------------------------------------------------------------
extern "C" void kernel_launch(void* const* d_in, const int* in_sizes, int n_in,
                              void* d_out, int out_size) {
    const float* x   = (const float*)d_in[0];
    const float* gw  = (const float*)d_in[1];
    const float* wfc = (const float*)d_in[2];
    const float* bfc = (const float*)d_in[3];
    const float* wpj = (const float*)d_in[4];
    const float* bpj = (const float*)d_in[5];
    float* out = (float*)d_out;

    cudaFuncSetAttribute(k_fc_mma,   cudaFuncAttributeMaxDynamicSharedMemorySize, SMEM_DYN);
    cudaFuncSetAttribute(k_proj_mma, cudaFuncAttributeMaxDynamicSharedMemorySize, SMEM_DYN);

    k_zero  <<<2048, 256>>>(out, out_size);                                    // 0
    k_gate  <<<T_ / 8, 256>>>(x, gw);                                          // 1
    k_quantD<<<NROWS_D / 8, 256>>>(x, wfc);                                    // 2
    k_fc_mma  <<<dim3(T_ / BM, F_ / BN, E_), NTH, SMEM_DYN>>>(bfc);            // 3 <- ncu
    k_quantF<<<E_ * D_, QTH>>>(wpj);                                           // 4
    k_quantH<<<TK_, QTH>>>();                                                  // 5
    k_proj_mma<<<dim3(T_ / BM, D_ / BN, E_), NTH, SMEM_DYN>>>(bpj, out);       // 6
}